// round 6
// baseline (speedup 1.0000x reference)
#include <cuda_runtime.h>
#include <cuda_fp16.h>
#include <cstdint>

#define MTOT 16384
#define EMB  1024
#define LSEQ 2048

// ---------------- scratch (allocation-free rule) ----------------
__device__ __half g_xh[MTOT * EMB];          // fp16 x
__device__ __half g_wqkv[EMB * 3 * EMB];     // fp16 [K][Wq|Wk|Wv] (ldb=3072)
__device__ __half g_wo[EMB * EMB];           // fp16 Wo
__device__ __half g_q[MTOT * EMB];
__device__ __half g_k[MTOT * EMB];
__device__ __half g_v[MTOT * EMB];
__device__ __half g_att[MTOT * EMB];         // scrambled attention output

// ---------------- GEMM config: 256x256 CTA tile, KC=32, 4 stages -----------
#define GKC 32
#define NKT (EMB / GKC)            // 32
#define A_LDH 40                   // halves per A smem row (32 + 8 pad)
#define B_LDH 264                  // halves per B smem row (256 + 8 pad)
#define A_STB (256 * A_LDH * 2)    // 20480
#define B_STB (GKC * B_LDH * 2)    // 16896
#define STG_B (A_STB + B_STB)      // 37376
#define G2_SMEM (4 * STG_B)        // 149504

// ---------------- helpers ----------------
__device__ __forceinline__ void cp16(void* s, const void* g) {
    unsigned sa = (unsigned)__cvta_generic_to_shared(s);
    asm volatile("cp.async.cg.shared.global [%0], [%1], 16;\n" :: "r"(sa), "l"(g));
}
__device__ __forceinline__ void cp_commit() {
    asm volatile("cp.async.commit_group;\n" ::);
}
template<int N>
__device__ __forceinline__ void cp_wait() {
    asm volatile("cp.async.wait_group %0;\n" :: "n"(N));
}
__device__ __forceinline__ void ldsm4(uint32_t* r, const __half* p) {
    uint32_t a = (uint32_t)__cvta_generic_to_shared(p);
    asm volatile("ldmatrix.sync.aligned.m8n8.x4.shared.b16 {%0,%1,%2,%3}, [%4];"
        : "=r"(r[0]), "=r"(r[1]), "=r"(r[2]), "=r"(r[3]) : "r"(a));
}
__device__ __forceinline__ void ldsm4t(uint32_t* r, const __half* p) {
    uint32_t a = (uint32_t)__cvta_generic_to_shared(p);
    asm volatile("ldmatrix.sync.aligned.m8n8.x4.trans.shared.b16 {%0,%1,%2,%3}, [%4];"
        : "=r"(r[0]), "=r"(r[1]), "=r"(r[2]), "=r"(r[3]) : "r"(a));
}
__device__ __forceinline__ void ldsm2(uint32_t* r, const __half* p) {
    uint32_t a = (uint32_t)__cvta_generic_to_shared(p);
    asm volatile("ldmatrix.sync.aligned.m8n8.x2.shared.b16 {%0,%1}, [%2];"
        : "=r"(r[0]), "=r"(r[1]) : "r"(a));
}
__device__ __forceinline__ void ldsm2t(uint32_t* r, const __half* p) {
    uint32_t a = (uint32_t)__cvta_generic_to_shared(p);
    asm volatile("ldmatrix.sync.aligned.m8n8.x2.trans.shared.b16 {%0,%1}, [%2];"
        : "=r"(r[0]), "=r"(r[1]) : "r"(a));
}
__device__ __forceinline__ void mma16816(float* c, const uint32_t* a, const uint32_t* b) {
    asm volatile(
        "mma.sync.aligned.m16n8k16.row.col.f32.f16.f16.f32 "
        "{%0,%1,%2,%3}, {%4,%5,%6,%7}, {%8,%9}, {%0,%1,%2,%3};"
        : "+f"(c[0]), "+f"(c[1]), "+f"(c[2]), "+f"(c[3])
        : "r"(a[0]), "r"(a[1]), "r"(a[2]), "r"(a[3]), "r"(b[0]), "r"(b[1]));
}

// ---------------------------------------------------------------------------
// 256x256 raw-mma fp16 GEMM. 512 threads, 16 warps of 64x64.
// BIAS=false: half output, column block selects among H0/H1/H2 (ldb may be 3072).
// BIAS=true : float output + bias, direct stores.
// ---------------------------------------------------------------------------
template<bool BIAS>
__device__ __forceinline__ void gemm_core2(
    const __half* __restrict__ A, const __half* __restrict__ B, int ldb,
    __half* __restrict__ H0, __half* __restrict__ H1, __half* __restrict__ H2,
    float* __restrict__ F, const float* __restrict__ bias)
{
    extern __shared__ char smem[];
    const int tid  = threadIdx.x;
    const int warp = tid >> 5;
    const int lane = tid & 31;
    const int bm = blockIdx.y * 256;
    const int bn = blockIdx.x * 256;
    const int wm = (warp >> 2) * 64;
    const int wn = (warp & 3) * 64;

    float c[4][8][4];
#pragma unroll
    for (int i = 0; i < 4; i++)
#pragma unroll
        for (int j = 0; j < 8; j++) {
            c[i][j][0] = 0.f; c[i][j][1] = 0.f; c[i][j][2] = 0.f; c[i][j][3] = 0.f;
        }

    auto issue = [&](int kt) {
        char* st = smem + (kt & 3) * STG_B;
#pragma unroll
        for (int i = 0; i < 2; i++) {          // A: 256x32 halves = 1024 chunks
            const int idx = tid + i * 512;
            const int row = idx >> 2, cc = idx & 3;
            cp16(st + row * (A_LDH * 2) + cc * 16,
                 A + (size_t)(bm + row) * EMB + kt * GKC + cc * 8);
        }
        char* stb = st + A_STB;
#pragma unroll
        for (int i = 0; i < 2; i++) {          // B: 32x256 halves = 1024 chunks
            const int idx = tid + i * 512;
            const int row = idx >> 5, cc = idx & 31;
            cp16(stb + row * (B_LDH * 2) + cc * 16,
                 B + (size_t)(kt * GKC + row) * ldb + bn + cc * 8);
        }
        cp_commit();
    };

    issue(0); issue(1); issue(2);

    for (int kt = 0; kt < NKT; ++kt) {
        cp_wait<2>();
        __syncthreads();
        if (kt + 3 < NKT) issue(kt + 3); else cp_commit();   // keep pending-count invariant

        const __half* sA = (const __half*)(smem + (kt & 3) * STG_B);
        const __half* sB = (const __half*)(smem + (kt & 3) * STG_B + A_STB);
#pragma unroll
        for (int kk = 0; kk < 2; ++kk) {
            uint32_t a[4][4], b[8][2];
#pragma unroll
            for (int i = 0; i < 4; i++)
                ldsm4(a[i], sA + (wm + i * 16 + (lane & 15)) * A_LDH
                              + kk * 16 + (lane >> 4) * 8);
#pragma unroll
            for (int j2 = 0; j2 < 4; j2++) {
                uint32_t t[4];
                ldsm4t(t, sB + (kk * 16 + (lane & 15)) * B_LDH
                            + wn + j2 * 16 + (lane >> 4) * 8);
                b[2 * j2][0] = t[0]; b[2 * j2][1] = t[1];
                b[2 * j2 + 1][0] = t[2]; b[2 * j2 + 1][1] = t[3];
            }
#pragma unroll
            for (int i = 0; i < 4; i++)
#pragma unroll
                for (int j = 0; j < 8; j++)
                    mma16816(c[i][j], a[i], b[j]);
        }
    }
    __syncthreads();

    const int r = lane >> 2, t = lane & 3;
    if (BIAS) {
        // direct coalesced float2 stores + bias
#pragma unroll
        for (int i = 0; i < 4; i++) {
#pragma unroll
            for (int j = 0; j < 8; j++) {
                const int col = bn + wn + j * 8 + 2 * t;
                const float2 bb = *(const float2*)(bias + col);
                const int row0 = bm + wm + i * 16 + r;
                float2 v0, v1;
                v0.x = c[i][j][0] + bb.x; v0.y = c[i][j][1] + bb.y;
                v1.x = c[i][j][2] + bb.x; v1.y = c[i][j][3] + bb.y;
                *(float2*)(F + (size_t)row0 * EMB + col) = v0;
                *(float2*)(F + (size_t)(row0 + 8) * EMB + col) = v1;
            }
        }
    } else {
        // stage halves in smem (stride 264: conflict-free), then 16B stores
        __half* sc = (__half*)smem;   // [256][264] halves = 135168 B
#pragma unroll
        for (int i = 0; i < 4; i++)
#pragma unroll
            for (int j = 0; j < 8; j++) {
                const int row0 = wm + i * 16 + r;
                const int col = wn + j * 8 + 2 * t;
                *(__half2*)(sc + row0 * B_LDH + col) =
                    __floats2half2_rn(c[i][j][0], c[i][j][1]);
                *(__half2*)(sc + (row0 + 8) * B_LDH + col) =
                    __floats2half2_rn(c[i][j][2], c[i][j][3]);
            }
        __syncthreads();
        const int z = bn >> 10;
        __half* O = (z == 0) ? H0 : (z == 1) ? H1 : H2;
        const int bnl = bn & 1023;
#pragma unroll
        for (int i = 0; i < 16; i++) {          // 256x256 halves = 8192 chunks
            const int idx = tid + i * 512;
            const int row = idx >> 5, cc = idx & 31;
            *(uint4*)(O + (size_t)(bm + row) * EMB + bnl + cc * 8) =
                *(const uint4*)(sc + row * B_LDH + cc * 8);
        }
    }
}

__global__ void __launch_bounds__(512, 1) gemm_qkv_k(
    const __half* __restrict__ A, const __half* __restrict__ W,
    __half* __restrict__ Q, __half* __restrict__ K, __half* __restrict__ V)
{
    gemm_core2<false>(A, W, 3 * EMB, Q, K, V, nullptr, nullptr);
}

__global__ void __launch_bounds__(512, 1) gemm_out_k(
    const __half* __restrict__ A, const __half* __restrict__ W,
    float* __restrict__ C, const float* __restrict__ bias)
{
    gemm_core2<true>(A, W, EMB, nullptr, nullptr, nullptr, C, bias);
}

// ---------------------------------------------------------------------------
// conversions
// ---------------------------------------------------------------------------
__global__ void __launch_bounds__(256) cvt_f2h(
    const float* __restrict__ in, __half* __restrict__ out, int n8)
{
    const int i = blockIdx.x * blockDim.x + threadIdx.x;
    if (i < n8) {
        float4 a = ((const float4*)in)[2 * i];
        float4 b = ((const float4*)in)[2 * i + 1];
        __half2 h0 = __floats2half2_rn(a.x, a.y);
        __half2 h1 = __floats2half2_rn(a.z, a.w);
        __half2 h2 = __floats2half2_rn(b.x, b.y);
        __half2 h3 = __floats2half2_rn(b.z, b.w);
        uint4 u;
        u.x = *(const unsigned*)&h0; u.y = *(const unsigned*)&h1;
        u.z = *(const unsigned*)&h2; u.w = *(const unsigned*)&h3;
        ((uint4*)out)[i] = u;
    }
}

// pack Wq|Wk|Wv columns into [K][3072]
__global__ void __launch_bounds__(256) cvt_wqkv(
    const float* __restrict__ Wq, const float* __restrict__ Wk,
    const float* __restrict__ Wv, __half* __restrict__ out, int n8)
{
    const int z = blockIdx.y;
    const float* in = (z == 0) ? Wq : (z == 1) ? Wk : Wv;
    const int i = blockIdx.x * blockDim.x + threadIdx.x;
    if (i < n8) {
        const int k = i >> 7;          // row (1024/8 = 128 chunks per row)
        const int cc = i & 127;
        float4 a = ((const float4*)in)[2 * i];
        float4 b = ((const float4*)in)[2 * i + 1];
        __half2 h0 = __floats2half2_rn(a.x, a.y);
        __half2 h1 = __floats2half2_rn(a.z, a.w);
        __half2 h2 = __floats2half2_rn(b.x, b.y);
        __half2 h3 = __floats2half2_rn(b.z, b.w);
        uint4 u;
        u.x = *(const unsigned*)&h0; u.y = *(const unsigned*)&h1;
        u.z = *(const unsigned*)&h2; u.w = *(const unsigned*)&h3;
        *(uint4*)(out + (size_t)k * (3 * EMB) + z * EMB + cc * 8) = u;
    }
}

// ---------------------------------------------------------------------------
// Tensor-core per-token attention (proven in R5; unchanged).
// ---------------------------------------------------------------------------
__global__ void __launch_bounds__(128) attn_mma(
    const __half* __restrict__ q, const __half* __restrict__ k,
    const __half* __restrict__ v, __half* __restrict__ o)
{
    __shared__ __align__(16) __half sm[4][3][16 * 72];
    const int wid  = threadIdx.x >> 5;
    const int lane = threadIdx.x & 31;
    const int tok = blockIdx.x * 4 + wid;
    const int n = tok >> 11;
    const int l = tok & 2047;
    const size_t base = (size_t)tok * EMB;

    __half* sQ = sm[wid][0];
    __half* sK = sm[wid][1];
    __half* sV = sm[wid][2];

    {
        const uint4* gq = (const uint4*)(q + base);
        const uint4* gk = (const uint4*)(k + base);
        const uint4* gv = (const uint4*)(v + base);
#pragma unroll
        for (int i = 0; i < 4; i++) {
            const int idx = lane + i * 32;
            const int row = idx >> 3, c = idx & 7;
            const int so = row * 72 + c * 8;
            *(uint4*)(sQ + so) = gq[idx];
            *(uint4*)(sK + so) = gk[idx];
            *(uint4*)(sV + so) = gv[idx];
        }
    }
    __syncwarp();

    float e0[4] = {0.f, 0.f, 0.f, 0.f};
    float e1[4] = {0.f, 0.f, 0.f, 0.f};
#pragma unroll
    for (int kc = 0; kc < 4; kc++) {
        uint32_t a[4], b0[2], b1[2];
        ldsm4(a, sQ + (lane & 15) * 72 + kc * 16 + (lane >> 4) * 8);
        const int krow = (lane & 7);
        const int koff = kc * 16 + ((lane >> 3) & 1) * 8;
        ldsm2(b0, sK + krow * 72 + koff);
        ldsm2(b1, sK + (8 + krow) * 72 + koff);
        mma16816(e0, a, b0);
        mma16816(e1, a, b1);
    }

    const float scl = 0.03125f;
    float v00 = e0[0] * scl, v01 = e0[1] * scl, v02 = e1[0] * scl, v03 = e1[1] * scl;
    float v10 = e0[2] * scl, v11 = e0[3] * scl, v12 = e1[2] * scl, v13 = e1[3] * scl;
    float m0 = fmaxf(fmaxf(v00, v01), fmaxf(v02, v03));
    float m1 = fmaxf(fmaxf(v10, v11), fmaxf(v12, v13));
    m0 = fmaxf(m0, __shfl_xor_sync(0xffffffffu, m0, 1));
    m0 = fmaxf(m0, __shfl_xor_sync(0xffffffffu, m0, 2));
    m1 = fmaxf(m1, __shfl_xor_sync(0xffffffffu, m1, 1));
    m1 = fmaxf(m1, __shfl_xor_sync(0xffffffffu, m1, 2));
    v00 = __expf(v00 - m0); v01 = __expf(v01 - m0); v02 = __expf(v02 - m0); v03 = __expf(v03 - m0);
    v10 = __expf(v10 - m1); v11 = __expf(v11 - m1); v12 = __expf(v12 - m1); v13 = __expf(v13 - m1);
    float s0 = v00 + v01 + v02 + v03;
    float s1 = v10 + v11 + v12 + v13;
    s0 += __shfl_xor_sync(0xffffffffu, s0, 1); s0 += __shfl_xor_sync(0xffffffffu, s0, 2);
    s1 += __shfl_xor_sync(0xffffffffu, s1, 1); s1 += __shfl_xor_sync(0xffffffffu, s1, 2);
    const float i0 = 1.0f / s0, i1 = 1.0f / s1;

    uint32_t pa[4];
    __half2 h;
    h = __floats2half2_rn(v00 * i0, v01 * i0); pa[0] = *(const uint32_t*)&h;
    h = __floats2half2_rn(v10 * i1, v11 * i1); pa[1] = *(const uint32_t*)&h;
    h = __floats2half2_rn(v02 * i0, v03 * i0); pa[2] = *(const uint32_t*)&h;
    h = __floats2half2_rn(v12 * i1, v13 * i1); pa[3] = *(const uint32_t*)&h;

    const int r  = lane >> 2;
    const int t  = lane & 3;
    const int li = l & 15;
    const int lh = l >> 4;
    const int vrow = (lane & 7) + ((lane >> 3) & 1) * 8;
    const size_t rbase0 = ((size_t)n * LSEQ + r * 128 + lh) * EMB + li * 64;
    const size_t rbase1 = ((size_t)n * LSEQ + (r + 8) * 128 + lh) * EMB + li * 64;
#pragma unroll
    for (int nb = 0; nb < 8; nb++) {
        uint32_t b[2];
        ldsm2t(b, sV + vrow * 72 + nb * 8);
        float c[4] = {0.f, 0.f, 0.f, 0.f};
        mma16816(c, pa, b);
        const int d = nb * 8 + 2 * t;
        __half2 o0 = __floats2half2_rn(c[0], c[1]);
        __half2 o1 = __floats2half2_rn(c[2], c[3]);
        *(__half2*)(o + rbase0 + d) = o0;
        *(__half2*)(o + rbase1 + d) = o1;
    }
}

// ---------------------------------------------------------------------------
extern "C" void kernel_launch(void* const* d_in, const int* in_sizes, int n_in,
                              void* d_out, int out_size)
{
    const float* x  = (const float*)d_in[0];
    const float* Wv = (const float*)d_in[1];
    const float* Wk = (const float*)d_in[2];
    const float* Wq = (const float*)d_in[3];
    const float* Wo = (const float*)d_in[4];
    const float* bo = (const float*)d_in[5];
    float* out = (float*)d_out;

    void *pxh, *pwqkv, *pwo, *pq, *pk, *pv, *pa;
    cudaGetSymbolAddress(&pxh, g_xh);
    cudaGetSymbolAddress(&pwqkv, g_wqkv);
    cudaGetSymbolAddress(&pwo, g_wo);
    cudaGetSymbolAddress(&pq, g_q);
    cudaGetSymbolAddress(&pk, g_k);
    cudaGetSymbolAddress(&pv, g_v);
    cudaGetSymbolAddress(&pa, g_att);
    __half* xh    = (__half*)pxh;
    __half* wqkv  = (__half*)pwqkv;
    __half* wo    = (__half*)pwo;
    __half* qb = (__half*)pq;
    __half* kb = (__half*)pk;
    __half* vb = (__half*)pv;
    __half* ab = (__half*)pa;

    cudaFuncSetAttribute(gemm_qkv_k, cudaFuncAttributeMaxDynamicSharedMemorySize, G2_SMEM);
    cudaFuncSetAttribute(gemm_out_k, cudaFuncAttributeMaxDynamicSharedMemorySize, G2_SMEM);

    // 1) conversions
    const int xn8 = MTOT * EMB / 8;
    cvt_f2h<<<(xn8 + 255) / 256, 256>>>(x, xh, xn8);
    const int wn8 = EMB * EMB / 8;
    cvt_wqkv<<<dim3((wn8 + 255) / 256, 3), 256>>>(Wq, Wk, Wv, wqkv, wn8);
    cvt_f2h<<<(wn8 + 255) / 256, 256>>>(Wo, wo, wn8);

    // 2) fused QKV projection: [16384,1024] @ [1024,3072]
    gemm_qkv_k<<<dim3(3 * EMB / 256, MTOT / 256), 512, G2_SMEM>>>(xh, wqkv, qb, kb, vb);

    // 3) per-token head attention (scrambled fp16 output)
    attn_mma<<<MTOT / 4, 128>>>(qb, kb, vb, ab);

    // 4) output projection + bias (fp32 out, direct stores)
    gemm_out_k<<<dim3(EMB / 256, MTOT / 256), 512, G2_SMEM>>>(ab, wo, out, bo);
}

// round 7
// speedup vs baseline: 2.5866x; 2.5866x over previous
#include <cuda_runtime.h>
#include <cuda_fp16.h>
#include <cstdint>

#define MTOT 16384
#define EMB  1024
#define LSEQ 2048

// ---------------- scratch (allocation-free rule) ----------------
__device__ __half g_xh[MTOT * EMB];          // fp16 x
__device__ __half g_wqkv[EMB * 3 * EMB];     // fp16 [K][Wq|Wk|Wv] (ldb=3072)
__device__ __half g_wo[EMB * EMB];           // fp16 Wo
__device__ __half g_q[MTOT * EMB];
__device__ __half g_k[MTOT * EMB];
__device__ __half g_v[MTOT * EMB];
__device__ __half g_att[MTOT * EMB];         // scrambled attention output

// ---------------- GEMM config: 128x128 CTA tile, KC=64, 3 stages -----------
#define GKC 64
#define NKT (EMB / GKC)            // 16
#define A_LDH 72                   // halves per A smem row (64 + 8 pad) = 144B
#define B_LDH 136                  // halves per B smem row (128 + 8 pad) = 272B
#define A_STB (128 * A_LDH * 2)    // 18432
#define B_STB (GKC * B_LDH * 2)    // 17408
#define STG_B (A_STB + B_STB)      // 35840
#define G_SMEM (3 * STG_B)         // 107520

// ---------------- helpers ----------------
__device__ __forceinline__ void cp16(void* s, const void* g) {
    unsigned sa = (unsigned)__cvta_generic_to_shared(s);
    asm volatile("cp.async.cg.shared.global [%0], [%1], 16;\n" :: "r"(sa), "l"(g));
}
__device__ __forceinline__ void cp_commit() {
    asm volatile("cp.async.commit_group;\n" ::);
}
template<int N>
__device__ __forceinline__ void cp_wait() {
    asm volatile("cp.async.wait_group %0;\n" :: "n"(N));
}
__device__ __forceinline__ void ldsm4(uint32_t* r, const __half* p) {
    uint32_t a = (uint32_t)__cvta_generic_to_shared(p);
    asm volatile("ldmatrix.sync.aligned.m8n8.x4.shared.b16 {%0,%1,%2,%3}, [%4];"
        : "=r"(r[0]), "=r"(r[1]), "=r"(r[2]), "=r"(r[3]) : "r"(a));
}
__device__ __forceinline__ void ldsm4t(uint32_t* r, const __half* p) {
    uint32_t a = (uint32_t)__cvta_generic_to_shared(p);
    asm volatile("ldmatrix.sync.aligned.m8n8.x4.trans.shared.b16 {%0,%1,%2,%3}, [%4];"
        : "=r"(r[0]), "=r"(r[1]), "=r"(r[2]), "=r"(r[3]) : "r"(a));
}
__device__ __forceinline__ void ldsm2(uint32_t* r, const __half* p) {
    uint32_t a = (uint32_t)__cvta_generic_to_shared(p);
    asm volatile("ldmatrix.sync.aligned.m8n8.x2.shared.b16 {%0,%1}, [%2];"
        : "=r"(r[0]), "=r"(r[1]) : "r"(a));
}
__device__ __forceinline__ void ldsm2t(uint32_t* r, const __half* p) {
    uint32_t a = (uint32_t)__cvta_generic_to_shared(p);
    asm volatile("ldmatrix.sync.aligned.m8n8.x2.trans.shared.b16 {%0,%1}, [%2];"
        : "=r"(r[0]), "=r"(r[1]) : "r"(a));
}
__device__ __forceinline__ void mma16816(float* c, const uint32_t* a, const uint32_t* b) {
    asm volatile(
        "mma.sync.aligned.m16n8k16.row.col.f32.f16.f16.f32 "
        "{%0,%1,%2,%3}, {%4,%5,%6,%7}, {%8,%9}, {%0,%1,%2,%3};"
        : "+f"(c[0]), "+f"(c[1]), "+f"(c[2]), "+f"(c[3])
        : "r"(a[0]), "r"(a[1]), "r"(a[2]), "r"(a[3]), "r"(b[0]), "r"(b[1]));
}

// ---------------------------------------------------------------------------
// 128x128 raw-mma fp16 GEMM, 128 threads (4 warps of 64x64), 3-stage cp.async.
// BIAS=false: half output; column block selects among H0/H1/H2 (ldb may be 3072).
// BIAS=true : float output + bias, direct coalesced stores.
// ---------------------------------------------------------------------------
template<bool BIAS>
__device__ __forceinline__ void gemm_core(
    const __half* __restrict__ A, const __half* __restrict__ B, int ldb,
    __half* __restrict__ H0, __half* __restrict__ H1, __half* __restrict__ H2,
    float* __restrict__ F, const float* __restrict__ bias)
{
    extern __shared__ char smem[];
    const int tid  = threadIdx.x;
    const int warp = tid >> 5;
    const int lane = tid & 31;
    const int bm = blockIdx.y * 128;
    const int bn = blockIdx.x * 128;
    const int wm = (warp >> 1) * 64;
    const int wn = (warp & 1) * 64;

    float c[4][8][4];
#pragma unroll
    for (int i = 0; i < 4; i++)
#pragma unroll
        for (int j = 0; j < 8; j++) {
            c[i][j][0] = 0.f; c[i][j][1] = 0.f; c[i][j][2] = 0.f; c[i][j][3] = 0.f;
        }

    auto issue = [&](int kt) {
        char* st = smem + (kt % 3) * STG_B;
#pragma unroll
        for (int i = 0; i < 8; i++) {          // A: 128x64 halves = 1024 chunks
            const int idx = tid + i * 128;
            const int row = idx >> 3, cc = idx & 7;
            cp16(st + row * (A_LDH * 2) + cc * 16,
                 A + (size_t)(bm + row) * EMB + kt * GKC + cc * 8);
        }
        char* stb = st + A_STB;
#pragma unroll
        for (int i = 0; i < 8; i++) {          // B: 64x128 halves = 1024 chunks
            const int idx = tid + i * 128;
            const int row = idx >> 4, cc = idx & 15;
            cp16(stb + row * (B_LDH * 2) + cc * 16,
                 B + (size_t)(kt * GKC + row) * ldb + bn + cc * 8);
        }
        cp_commit();
    };

    issue(0); issue(1);

    for (int kt = 0; kt < NKT; ++kt) {
        if (kt == NKT - 1) cp_wait<0>(); else cp_wait<1>();
        __syncthreads();
        if (kt + 2 < NKT) issue(kt + 2);

        const __half* sA = (const __half*)(smem + (kt % 3) * STG_B);
        const __half* sB = (const __half*)(smem + (kt % 3) * STG_B + A_STB);
#pragma unroll
        for (int kk = 0; kk < 4; ++kk) {
            uint32_t a[4][4], b[8][2];
#pragma unroll
            for (int i = 0; i < 4; i++)
                ldsm4(a[i], sA + (wm + i * 16 + (lane & 15)) * A_LDH
                              + kk * 16 + (lane >> 4) * 8);
#pragma unroll
            for (int j2 = 0; j2 < 4; j2++) {
                uint32_t t[4];
                ldsm4t(t, sB + (kk * 16 + (lane & 15)) * B_LDH
                            + wn + j2 * 16 + (lane >> 4) * 8);
                b[2 * j2][0] = t[0]; b[2 * j2][1] = t[1];
                b[2 * j2 + 1][0] = t[2]; b[2 * j2 + 1][1] = t[3];
            }
#pragma unroll
            for (int i = 0; i < 4; i++)
#pragma unroll
                for (int j = 0; j < 8; j++)
                    mma16816(c[i][j], a[i], b[j]);
        }
    }

    const int r = lane >> 2, t = lane & 3;
    if (BIAS) {
        // direct coalesced float2 stores + bias
#pragma unroll
        for (int i = 0; i < 4; i++) {
#pragma unroll
            for (int j = 0; j < 8; j++) {
                const int col = bn + wn + j * 8 + 2 * t;
                const float2 bb = *(const float2*)(bias + col);
                const int row0 = bm + wm + i * 16 + r;
                float2 v0, v1;
                v0.x = c[i][j][0] + bb.x; v0.y = c[i][j][1] + bb.y;
                v1.x = c[i][j][2] + bb.x; v1.y = c[i][j][3] + bb.y;
                *(float2*)(F + (size_t)row0 * EMB + col) = v0;
                *(float2*)(F + (size_t)(row0 + 8) * EMB + col) = v1;
            }
        }
    } else {
        // stage halves in smem (stride B_LDH, conflict-free), then 16B stores
        __syncthreads();
        __half* sc = (__half*)smem;   // [128][136] halves = 34816 B
#pragma unroll
        for (int i = 0; i < 4; i++)
#pragma unroll
            for (int j = 0; j < 8; j++) {
                const int row0 = wm + i * 16 + r;
                const int col = wn + j * 8 + 2 * t;
                *(__half2*)(sc + row0 * B_LDH + col) =
                    __floats2half2_rn(c[i][j][0], c[i][j][1]);
                *(__half2*)(sc + (row0 + 8) * B_LDH + col) =
                    __floats2half2_rn(c[i][j][2], c[i][j][3]);
            }
        __syncthreads();
        const int z = bn >> 10;
        __half* O = (z == 0) ? H0 : (z == 1) ? H1 : H2;
        const int bnl = bn & 1023;
#pragma unroll
        for (int i = 0; i < 16; i++) {          // 128x128 halves = 2048 chunks
            const int idx = tid + i * 128;
            const int row = idx >> 4, cc = idx & 15;
            *(uint4*)(O + (size_t)(bm + row) * EMB + bnl + cc * 8) =
                *(const uint4*)(sc + row * B_LDH + cc * 8);
        }
    }
}

__global__ void __launch_bounds__(128, 2) gemm_qkv_k(
    const __half* __restrict__ A, const __half* __restrict__ W,
    __half* __restrict__ Q, __half* __restrict__ K, __half* __restrict__ V)
{
    gemm_core<false>(A, W, 3 * EMB, Q, K, V, nullptr, nullptr);
}

__global__ void __launch_bounds__(128, 2) gemm_out_k(
    const __half* __restrict__ A, const __half* __restrict__ W,
    float* __restrict__ C, const float* __restrict__ bias)
{
    gemm_core<true>(A, W, EMB, nullptr, nullptr, nullptr, C, bias);
}

// ---------------------------------------------------------------------------
// conversions
// ---------------------------------------------------------------------------
__global__ void __launch_bounds__(256) cvt_f2h(
    const float* __restrict__ in, __half* __restrict__ out, int n8)
{
    const int i = blockIdx.x * blockDim.x + threadIdx.x;
    if (i < n8) {
        float4 a = ((const float4*)in)[2 * i];
        float4 b = ((const float4*)in)[2 * i + 1];
        __half2 h0 = __floats2half2_rn(a.x, a.y);
        __half2 h1 = __floats2half2_rn(a.z, a.w);
        __half2 h2 = __floats2half2_rn(b.x, b.y);
        __half2 h3 = __floats2half2_rn(b.z, b.w);
        uint4 u;
        u.x = *(const unsigned*)&h0; u.y = *(const unsigned*)&h1;
        u.z = *(const unsigned*)&h2; u.w = *(const unsigned*)&h3;
        ((uint4*)out)[i] = u;
    }
}

// pack Wq|Wk|Wv columns into [K][3072]
__global__ void __launch_bounds__(256) cvt_wqkv(
    const float* __restrict__ Wq, const float* __restrict__ Wk,
    const float* __restrict__ Wv, __half* __restrict__ out, int n8)
{
    const int z = blockIdx.y;
    const float* in = (z == 0) ? Wq : (z == 1) ? Wk : Wv;
    const int i = blockIdx.x * blockDim.x + threadIdx.x;
    if (i < n8) {
        const int k = i >> 7;
        const int cc = i & 127;
        float4 a = ((const float4*)in)[2 * i];
        float4 b = ((const float4*)in)[2 * i + 1];
        __half2 h0 = __floats2half2_rn(a.x, a.y);
        __half2 h1 = __floats2half2_rn(a.z, a.w);
        __half2 h2 = __floats2half2_rn(b.x, b.y);
        __half2 h3 = __floats2half2_rn(b.z, b.w);
        uint4 u;
        u.x = *(const unsigned*)&h0; u.y = *(const unsigned*)&h1;
        u.z = *(const unsigned*)&h2; u.w = *(const unsigned*)&h3;
        *(uint4*)(out + (size_t)k * (3 * EMB) + z * EMB + cc * 8) = u;
    }
}

// ---------------------------------------------------------------------------
// Tensor-core per-token attention (proven in R5; unchanged).
// ---------------------------------------------------------------------------
__global__ void __launch_bounds__(128) attn_mma(
    const __half* __restrict__ q, const __half* __restrict__ k,
    const __half* __restrict__ v, __half* __restrict__ o)
{
    __shared__ __align__(16) __half sm[4][3][16 * 72];
    const int wid  = threadIdx.x >> 5;
    const int lane = threadIdx.x & 31;
    const int tok = blockIdx.x * 4 + wid;
    const int n = tok >> 11;
    const int l = tok & 2047;
    const size_t base = (size_t)tok * EMB;

    __half* sQ = sm[wid][0];
    __half* sK = sm[wid][1];
    __half* sV = sm[wid][2];

    {
        const uint4* gq = (const uint4*)(q + base);
        const uint4* gk = (const uint4*)(k + base);
        const uint4* gv = (const uint4*)(v + base);
#pragma unroll
        for (int i = 0; i < 4; i++) {
            const int idx = lane + i * 32;
            const int row = idx >> 3, c = idx & 7;
            const int so = row * 72 + c * 8;
            *(uint4*)(sQ + so) = gq[idx];
            *(uint4*)(sK + so) = gk[idx];
            *(uint4*)(sV + so) = gv[idx];
        }
    }
    __syncwarp();

    float e0[4] = {0.f, 0.f, 0.f, 0.f};
    float e1[4] = {0.f, 0.f, 0.f, 0.f};
#pragma unroll
    for (int kc = 0; kc < 4; kc++) {
        uint32_t a[4], b0[2], b1[2];
        ldsm4(a, sQ + (lane & 15) * 72 + kc * 16 + (lane >> 4) * 8);
        const int krow = (lane & 7);
        const int koff = kc * 16 + ((lane >> 3) & 1) * 8;
        ldsm2(b0, sK + krow * 72 + koff);
        ldsm2(b1, sK + (8 + krow) * 72 + koff);
        mma16816(e0, a, b0);
        mma16816(e1, a, b1);
    }

    const float scl = 0.03125f;
    float v00 = e0[0] * scl, v01 = e0[1] * scl, v02 = e1[0] * scl, v03 = e1[1] * scl;
    float v10 = e0[2] * scl, v11 = e0[3] * scl, v12 = e1[2] * scl, v13 = e1[3] * scl;
    float m0 = fmaxf(fmaxf(v00, v01), fmaxf(v02, v03));
    float m1 = fmaxf(fmaxf(v10, v11), fmaxf(v12, v13));
    m0 = fmaxf(m0, __shfl_xor_sync(0xffffffffu, m0, 1));
    m0 = fmaxf(m0, __shfl_xor_sync(0xffffffffu, m0, 2));
    m1 = fmaxf(m1, __shfl_xor_sync(0xffffffffu, m1, 1));
    m1 = fmaxf(m1, __shfl_xor_sync(0xffffffffu, m1, 2));
    v00 = __expf(v00 - m0); v01 = __expf(v01 - m0); v02 = __expf(v02 - m0); v03 = __expf(v03 - m0);
    v10 = __expf(v10 - m1); v11 = __expf(v11 - m1); v12 = __expf(v12 - m1); v13 = __expf(v13 - m1);
    float s0 = v00 + v01 + v02 + v03;
    float s1 = v10 + v11 + v12 + v13;
    s0 += __shfl_xor_sync(0xffffffffu, s0, 1); s0 += __shfl_xor_sync(0xffffffffu, s0, 2);
    s1 += __shfl_xor_sync(0xffffffffu, s1, 1); s1 += __shfl_xor_sync(0xffffffffu, s1, 2);
    const float i0 = 1.0f / s0, i1 = 1.0f / s1;

    uint32_t pa[4];
    __half2 h;
    h = __floats2half2_rn(v00 * i0, v01 * i0); pa[0] = *(const uint32_t*)&h;
    h = __floats2half2_rn(v10 * i1, v11 * i1); pa[1] = *(const uint32_t*)&h;
    h = __floats2half2_rn(v02 * i0, v03 * i0); pa[2] = *(const uint32_t*)&h;
    h = __floats2half2_rn(v12 * i1, v13 * i1); pa[3] = *(const uint32_t*)&h;

    const int r  = lane >> 2;
    const int t  = lane & 3;
    const int li = l & 15;
    const int lh = l >> 4;
    const int vrow = (lane & 7) + ((lane >> 3) & 1) * 8;
    const size_t rbase0 = ((size_t)n * LSEQ + r * 128 + lh) * EMB + li * 64;
    const size_t rbase1 = ((size_t)n * LSEQ + (r + 8) * 128 + lh) * EMB + li * 64;
#pragma unroll
    for (int nb = 0; nb < 8; nb++) {
        uint32_t b[2];
        ldsm2t(b, sV + vrow * 72 + nb * 8);
        float c[4] = {0.f, 0.f, 0.f, 0.f};
        mma16816(c, pa, b);
        const int d = nb * 8 + 2 * t;
        __half2 o0 = __floats2half2_rn(c[0], c[1]);
        __half2 o1 = __floats2half2_rn(c[2], c[3]);
        *(__half2*)(o + rbase0 + d) = o0;
        *(__half2*)(o + rbase1 + d) = o1;
    }
}

// ---------------------------------------------------------------------------
extern "C" void kernel_launch(void* const* d_in, const int* in_sizes, int n_in,
                              void* d_out, int out_size)
{
    const float* x  = (const float*)d_in[0];
    const float* Wv = (const float*)d_in[1];
    const float* Wk = (const float*)d_in[2];
    const float* Wq = (const float*)d_in[3];
    const float* Wo = (const float*)d_in[4];
    const float* bo = (const float*)d_in[5];
    float* out = (float*)d_out;

    void *pxh, *pwqkv, *pwo, *pq, *pk, *pv, *pa;
    cudaGetSymbolAddress(&pxh, g_xh);
    cudaGetSymbolAddress(&pwqkv, g_wqkv);
    cudaGetSymbolAddress(&pwo, g_wo);
    cudaGetSymbolAddress(&pq, g_q);
    cudaGetSymbolAddress(&pk, g_k);
    cudaGetSymbolAddress(&pv, g_v);
    cudaGetSymbolAddress(&pa, g_att);
    __half* xh    = (__half*)pxh;
    __half* wqkv  = (__half*)pwqkv;
    __half* wo    = (__half*)pwo;
    __half* qb = (__half*)pq;
    __half* kb = (__half*)pk;
    __half* vb = (__half*)pv;
    __half* ab = (__half*)pa;

    cudaFuncSetAttribute(gemm_qkv_k, cudaFuncAttributeMaxDynamicSharedMemorySize, G_SMEM);
    cudaFuncSetAttribute(gemm_out_k, cudaFuncAttributeMaxDynamicSharedMemorySize, G_SMEM);

    // 1) conversions
    const int xn8 = MTOT * EMB / 8;
    cvt_f2h<<<(xn8 + 255) / 256, 256>>>(x, xh, xn8);
    const int wn8 = EMB * EMB / 8;
    cvt_wqkv<<<dim3((wn8 + 255) / 256, 3), 256>>>(Wq, Wk, Wv, wqkv, wn8);
    cvt_f2h<<<(wn8 + 255) / 256, 256>>>(Wo, wo, wn8);

    // 2) fused QKV projection: [16384,1024] @ [1024,3072]
    gemm_qkv_k<<<dim3(3 * EMB / 128, MTOT / 128), 128, G_SMEM>>>(xh, wqkv, qb, kb, vb);

    // 3) per-token head attention (scrambled fp16 output)
    attn_mma<<<MTOT / 4, 128>>>(qb, kb, vb, ab);

    // 4) output projection + bias (fp32 out, direct stores)
    gemm_out_k<<<dim3(EMB / 128, MTOT / 128), 128, G_SMEM>>>(ab, wo, out, bo);
}